// round 9
// baseline (speedup 1.0000x reference)
#include <cuda_runtime.h>
#include <cuda_fp16.h>
#include <math.h>

// Caps1D dynamic routing — round 8.
// Two batch elements per CTA share one W[k] register stream (halves W L2
// traffic and phase-1 loads per output). u_ji fp16 register-resident for both
// b's (80 regs); 1 CTA/SM, grid 1024. Logit dot sweeps in dual-accumulator
// HFMA2 (v broadcast as half2); exp-weighted S sweeps remain fp32.

namespace {
constexpr int T    = 512;
constexpr int Rdim = 2336;
constexpr int Pdim = 16;
constexpr int Kdim = 2;
constexpr int Bdim = 1024;
constexpr int NW   = T / 32;
constexpr int J    = 5;                    // rows per thread
constexpr int WCONV = Kdim * J * 8 * 512;  // int4 elements in packed W
}

// Packed fp16 W: [k][j][c][t] -> int4. c = 2*m + hc; int4 holds 4 half2
// covering p = hc*8 .. hc*8+7 for that m. Rows >= Rdim are zero.
__device__ int4 W2dev[WCONV];

__global__ void convert_w_kernel(const float* __restrict__ W) {
    const int idx = blockIdx.x * blockDim.x + threadIdx.x;
    if (idx >= WCONV) return;
    const int t  = idx & 511;
    const int c  = (idx >> 9) & 7;
    const int kj = idx >> 12;
    const int j  = kj % J;
    const int k  = kj / J;
    const int row = j * 512 + t;
    const int m   = c >> 1;
    const int hc  = c & 1;
    int4 o = make_int4(0, 0, 0, 0);
    if (row < Rdim) {
        const float4* src = reinterpret_cast<const float4*>(W)
                          + ((size_t)(k * Rdim + row) * 4 + m) * 4 + hc * 2;
        float4 a = src[0];
        float4 b = src[1];
        __half2 h0 = __floats2half2_rn(a.x, a.y);
        __half2 h1 = __floats2half2_rn(a.z, a.w);
        __half2 h2 = __floats2half2_rn(b.x, b.y);
        __half2 h3 = __floats2half2_rn(b.z, b.w);
        o.x = *reinterpret_cast<int*>(&h0);
        o.y = *reinterpret_cast<int*>(&h1);
        o.z = *reinterpret_cast<int*>(&h2);
        o.w = *reinterpret_cast<int*>(&h3);
    }
    W2dev[idx] = o;
}

__device__ __forceinline__ float blockMaxF(float v, volatile float* red, int lane, int wid) {
    #pragma unroll
    for (int o = 16; o >= 1; o >>= 1) v = fmaxf(v, __shfl_xor_sync(0xffffffffu, v, o));
    __syncthreads();
    if (lane == 0) red[wid] = v;
    __syncthreads();
    float r = -3.0e38f;
    #pragma unroll
    for (int w = 0; w < NW; ++w) r = fmaxf(r, red[w]);
    return r;
}

__device__ __forceinline__ float blockSumF(float v, volatile float* red, int lane, int wid) {
    #pragma unroll
    for (int o = 16; o >= 1; o >>= 1) v += __shfl_xor_sync(0xffffffffu, v, o);
    __syncthreads();
    if (lane == 0) red[wid] = v;
    __syncthreads();
    float r = 0.f;
    #pragma unroll
    for (int w = 0; w < NW; ++w) r += red[w];
    return r;
}

// Block-reduce s[16]; scale by pre; squash. v published as __half2[8].
__device__ __forceinline__ void blockReduceS(const float* s, float* redS,
                                             __half2* vbufh, float* misc,
                                             float pre, bool need_v,
                                             int t, int lane, int wid) {
    const unsigned F = 0xffffffffu;
    float r8[8];
    {
        const bool hi = (lane & 16) != 0;
        #pragma unroll
        for (int i = 0; i < 8; i++) {
            float send = hi ? s[i] : s[8 + i];
            float recv = __shfl_xor_sync(F, send, 16);
            r8[i] = (hi ? s[8 + i] : s[i]) + recv;
        }
    }
    float r4[4];
    {
        const bool hi = (lane & 8) != 0;
        #pragma unroll
        for (int i = 0; i < 4; i++) {
            float send = hi ? r8[i] : r8[4 + i];
            float recv = __shfl_xor_sync(F, send, 8);
            r4[i] = (hi ? r8[4 + i] : r8[i]) + recv;
        }
    }
    #pragma unroll
    for (int o = 4; o >= 1; o >>= 1) {
        #pragma unroll
        for (int i = 0; i < 4; i++) r4[i] += __shfl_xor_sync(F, r4[i], o);
    }
    __syncthreads();
    if ((lane & 7) == 0) {
        const int quad = ((lane >> 4) & 1) * 2 + ((lane >> 3) & 1);
        float4 v4 = make_float4(r4[0], r4[1], r4[2], r4[3]);
        *reinterpret_cast<float4*>(&redS[wid * Pdim + quad * 4]) = v4;
    }
    __syncthreads();
    if (t < Pdim) {
        float acc = 0.f;
        #pragma unroll
        for (int w = 0; w < NW; ++w) acc += redS[w * Pdim + t];
        acc *= pre;
        float nrm = acc * acc;
        #pragma unroll
        for (int o = 8; o >= 1; o >>= 1) nrm += __shfl_xor_sync(0x0000ffffu, nrm, o);
        if (need_v) {
            float vf = sqrtf(nrm) / (1.f + nrm);
            float vv = acc * vf;
            float partner = __shfl_xor_sync(0x0000ffffu, vv, 1);
            if ((t & 1) == 0) vbufh[t >> 1] = __floats2half2_rn(vv, partner);
        }
        if (t == 0) *misc = nrm;
    }
    __syncthreads();
}

// Dual-accumulator fp16 dot: <h[0..7], vh[0..7]> (16 scalar products).
__device__ __forceinline__ float dot16h(const __half2* hj, const __half2* vh) {
    __half2 a = __hmul2(hj[0], vh[0]);
    __half2 b = __hmul2(hj[1], vh[1]);
    a = __hfma2(hj[2], vh[2], a);  b = __hfma2(hj[3], vh[3], b);
    a = __hfma2(hj[4], vh[4], a);  b = __hfma2(hj[5], vh[5], b);
    a = __hfma2(hj[6], vh[6], a);  b = __hfma2(hj[7], vh[7], b);
    float2 fa = __half22float2(a);
    float2 fb = __half22float2(b);
    return (fa.x + fa.y) + (fb.x + fb.y);
}

__global__ __launch_bounds__(T, 1)
void caps_routing_kernel(const float* __restrict__ u,
                         float* __restrict__ out) {
    __shared__ float   redS[NW * Pdim];
    __shared__ float   redW[NW];
    __shared__ __half2 vbufh[Pdim / 2];
    __shared__ float   miscS;

    const int t     = threadIdx.x;
    const int lane  = t & 31;
    const int wid   = t >> 5;
    const int bid   = blockIdx.x;
    const int bpair = bid >> 1;
    const int k     = bid & 1;
    const int b0    = 2 * bpair;
    const int b1    = b0 + 1;

    const float4* U4a = reinterpret_cast<const float4*>(u) + (size_t)b0 * Rdim;
    const float4* U4b = reinterpret_cast<const float4*>(u) + (size_t)b1 * Rdim;

    // ---------------- Phase 1: u_ji for both b's (shared W stream) ----------------
    __half2 h0[J][8], h1[J][8];

    #pragma unroll
    for (int j = 0; j < J; j++) {
        const int row  = j * 512 + t;
        const int rowc = row < Rdim ? row : Rdim - 1;   // clamp; W=0 masks tail
        float4 ua = U4a[rowc];
        float4 ub = U4b[rowc];
        __half2 a0 = __float2half2_rn(ua.x), a1 = __float2half2_rn(ua.y);
        __half2 a2 = __float2half2_rn(ua.z), a3 = __float2half2_rn(ua.w);
        __half2 c0 = __float2half2_rn(ub.x), c1 = __float2half2_rn(ub.y);
        __half2 c2 = __float2half2_rn(ub.z), c3 = __float2half2_rn(ub.w);

        const int4* Wp = W2dev + (size_t)(k * J + j) * 8 * 512 + t;
        #pragma unroll
        for (int hc = 0; hc < 2; hc++) {
            int4 w[4];
            #pragma unroll
            for (int mm = 0; mm < 4; mm++) w[mm] = Wp[(2 * mm + hc) * 512];  // coalesced
            const __half2* wh = reinterpret_cast<const __half2*>(w);
            #pragma unroll
            for (int i = 0; i < 4; i++) {
                __half2 accA = __hmul2(a3, wh[12 + i]);
                accA = __hfma2(a2, wh[8 + i], accA);
                accA = __hfma2(a1, wh[4 + i], accA);
                accA = __hfma2(a0, wh[0 + i], accA);
                h0[j][hc * 4 + i] = accA;
                __half2 accB = __hmul2(c3, wh[12 + i]);
                accB = __hfma2(c2, wh[8 + i], accB);
                accB = __hfma2(c1, wh[4 + i], accB);
                accB = __hfma2(c0, wh[0 + i], accB);
                h1[j][hc * 4 + i] = accB;
            }
        }
    }

    // ---------------- Phase 2: routing per b (sequential) ----------------
    auto run_routing = [&](__half2 (&h)[J][8], int oidx) {
        float d[J];
        #pragma unroll
        for (int j = 0; j < J; j++) d[j] = (j * 512 + t < Rdim) ? 0.f : -1.0e30f;

        __half2 vh[8];

        // ---- iteration 0: uniform c ----
        {
            float s[Pdim];
            #pragma unroll
            for (int pp = 0; pp < 8; pp++) {
                __half2 acc = h[0][pp];
                #pragma unroll
                for (int j = 1; j < J; j++) acc = __hadd2(acc, h[j][pp]);
                float2 f = __half22float2(acc);
                s[2 * pp]     = f.x;
                s[2 * pp + 1] = f.y;
            }
            blockReduceS(s, redS, vbufh, &miscS, 1.0f / (float)Rdim, true, t, lane, wid);
            #pragma unroll
            for (int pp = 0; pp < 8; pp++) vh[pp] = vbufh[pp];
            #pragma unroll
            for (int j = 0; j < J; j++) d[j] += dot16h(h[j], vh);  // tail: h=0 -> +0
        }

        // ---- iterations 1, 2 ----
        #pragma unroll
        for (int it = 1; it < 3; ++it) {
            float lmax = d[0];
            #pragma unroll
            for (int j = 1; j < J; j++) lmax = fmaxf(lmax, d[j]);
            const float gmax = blockMaxF(lmax, redW, lane, wid);

            float s[Pdim];
            #pragma unroll
            for (int p = 0; p < Pdim; p++) s[p] = 0.f;
            float lsum = 0.f;
            #pragma unroll
            for (int j = 0; j < J; j++) {
                float e = __expf(d[j] - gmax);   // invalid rows -> e = 0
                lsum += e;
                #pragma unroll
                for (int pp = 0; pp < 8; pp++) {
                    float2 f = __half22float2(h[j][pp]);
                    s[2 * pp]     = fmaf(e, f.x, s[2 * pp]);
                    s[2 * pp + 1] = fmaf(e, f.y, s[2 * pp + 1]);
                }
            }
            const float Z = blockSumF(lsum, redW, lane, wid);
            blockReduceS(s, redS, vbufh, &miscS, 1.0f / Z, it != 2, t, lane, wid);

            if (it == 2) break;
            #pragma unroll
            for (int pp = 0; pp < 8; pp++) vh[pp] = vbufh[pp];
            #pragma unroll
            for (int j = 0; j < J; j++) d[j] += dot16h(h[j], vh);
        }

        if (t == 0) {
            const float nrm = miscS;
            out[oidx] = nrm / (1.f + nrm);
        }
    };

    run_routing(h0, b0 * Kdim + k);
    run_routing(h1, b1 * Kdim + k);
}

extern "C" void kernel_launch(void* const* d_in, const int* in_sizes, int n_in,
                              void* d_out, int out_size) {
    const float* u = (const float*)d_in[0];   // [B, R, M] fp32
    const float* W = (const float*)d_in[1];   // [K, R, M, P] fp32
    float* out = (float*)d_out;               // [B, K] fp32

    convert_w_kernel<<<(WCONV + 255) / 256, 256>>>(W);
    caps_routing_kernel<<<(Bdim / 2) * Kdim, T>>>(u, out);
}

// round 10
// speedup vs baseline: 1.3378x; 1.3378x over previous
#include <cuda_runtime.h>
#include <cuda_fp16.h>
#include <math.h>

// Caps1D dynamic routing — round 10.
// R6 structure restored (1 b per CTA, 2 CTAs/SM) — R8 showed CTA overlap
// beats L2-byte savings for this barrier-dense kernel. Phase 2 slimmed:
//  * no softmax max-reduction (logits provably small; invalid rows -1e30 -> e=0)
//  * Z fused into the S[16] block reduction (one butterfly + one smem stage)
//  * logit dot sweeps in dual-accumulator HFMA2 (v broadcast as half2)
// Phase-2 barriers: 17 -> 9. Phase 1 unchanged: pure HFMA2 from prologue-
// packed fp16 W, 8 coalesced LDG.128 per row.

namespace {
constexpr int T    = 512;
constexpr int Rdim = 2336;
constexpr int Pdim = 16;
constexpr int Kdim = 2;
constexpr int Bdim = 1024;
constexpr int NW   = T / 32;
constexpr int J    = 5;                    // rows per thread
constexpr int WCONV = Kdim * J * 8 * 512;  // int4 elements in packed W
}

// Packed fp16 W: [k][j][c][t] -> int4. c = 2*m + hc; int4 holds 4 half2
// covering p = hc*8 .. hc*8+7 for that m. Rows >= Rdim are zero.
__device__ int4 W2dev[WCONV];

__global__ void convert_w_kernel(const float* __restrict__ W) {
    const int idx = blockIdx.x * blockDim.x + threadIdx.x;
    if (idx >= WCONV) return;
    const int t  = idx & 511;
    const int c  = (idx >> 9) & 7;
    const int kj = idx >> 12;
    const int j  = kj % J;
    const int k  = kj / J;
    const int row = j * 512 + t;
    const int m   = c >> 1;
    const int hc  = c & 1;
    int4 o = make_int4(0, 0, 0, 0);
    if (row < Rdim) {
        const float4* src = reinterpret_cast<const float4*>(W)
                          + ((size_t)(k * Rdim + row) * 4 + m) * 4 + hc * 2;
        float4 a = src[0];
        float4 b = src[1];
        __half2 h0 = __floats2half2_rn(a.x, a.y);
        __half2 h1 = __floats2half2_rn(a.z, a.w);
        __half2 h2 = __floats2half2_rn(b.x, b.y);
        __half2 h3 = __floats2half2_rn(b.z, b.w);
        o.x = *reinterpret_cast<int*>(&h0);
        o.y = *reinterpret_cast<int*>(&h1);
        o.z = *reinterpret_cast<int*>(&h2);
        o.w = *reinterpret_cast<int*>(&h3);
    }
    W2dev[idx] = o;
}

// Fused block reduction: S[16] (value-splitting butterfly -> smem) and
// optionally Z = block-sum(lsum) folded into the squash pre-scale.
// Publishes v as __half2[8] and the norm to *misc.
__device__ __forceinline__ void blockReduceSZ(const float* s, float lsum, bool use_z,
                                              float fixed_pre, float* redS,
                                              float* redW, __half2* vbufh,
                                              float* misc, bool need_v,
                                              int t, int lane, int wid) {
    const unsigned F = 0xffffffffu;
    float r8[8];
    {
        const bool hi = (lane & 16) != 0;
        #pragma unroll
        for (int i = 0; i < 8; i++) {
            float send = hi ? s[i] : s[8 + i];
            float recv = __shfl_xor_sync(F, send, 16);
            r8[i] = (hi ? s[8 + i] : s[i]) + recv;
        }
    }
    float r4[4];
    {
        const bool hi = (lane & 8) != 0;
        #pragma unroll
        for (int i = 0; i < 4; i++) {
            float send = hi ? r8[i] : r8[4 + i];
            float recv = __shfl_xor_sync(F, send, 8);
            r4[i] = (hi ? r8[4 + i] : r8[i]) + recv;
        }
    }
    #pragma unroll
    for (int o = 4; o >= 1; o >>= 1) {
        #pragma unroll
        for (int i = 0; i < 4; i++) r4[i] += __shfl_xor_sync(F, r4[i], o);
    }
    if (use_z) {
        #pragma unroll
        for (int o = 16; o >= 1; o >>= 1) lsum += __shfl_xor_sync(F, lsum, o);
    }
    __syncthreads();   // previous consumers of redS/redW/vbufh are done
    if ((lane & 7) == 0) {
        const int quad = ((lane >> 4) & 1) * 2 + ((lane >> 3) & 1);
        float4 v4 = make_float4(r4[0], r4[1], r4[2], r4[3]);
        *reinterpret_cast<float4*>(&redS[wid * Pdim + quad * 4]) = v4;
    }
    if (use_z && lane == 0) redW[wid] = lsum;
    __syncthreads();
    if (t < Pdim) {
        float acc = 0.f;
        #pragma unroll
        for (int w = 0; w < NW; ++w) acc += redS[w * Pdim + t];
        float pre = fixed_pre;
        if (use_z) {
            float Z = 0.f;
            #pragma unroll
            for (int w = 0; w < NW; ++w) Z += redW[w];
            pre = 1.0f / Z;
        }
        acc *= pre;
        float nrm = acc * acc;
        #pragma unroll
        for (int o = 8; o >= 1; o >>= 1) nrm += __shfl_xor_sync(0x0000ffffu, nrm, o);
        if (need_v) {
            float vf = sqrtf(nrm) / (1.f + nrm);
            float vv = acc * vf;
            float partner = __shfl_xor_sync(0x0000ffffu, vv, 1);
            if ((t & 1) == 0) vbufh[t >> 1] = __floats2half2_rn(vv, partner);
        }
        if (t == 0) *misc = nrm;
    }
    __syncthreads();
}

// Dual-accumulator fp16 dot: <h[0..7], vh[0..7]> (16 scalar products).
__device__ __forceinline__ float dot16h(const __half2* hj, const __half2* vh) {
    __half2 a = __hmul2(hj[0], vh[0]);
    __half2 b = __hmul2(hj[1], vh[1]);
    a = __hfma2(hj[2], vh[2], a);  b = __hfma2(hj[3], vh[3], b);
    a = __hfma2(hj[4], vh[4], a);  b = __hfma2(hj[5], vh[5], b);
    a = __hfma2(hj[6], vh[6], a);  b = __hfma2(hj[7], vh[7], b);
    float2 fa = __half22float2(a);
    float2 fb = __half22float2(b);
    return (fa.x + fa.y) + (fb.x + fb.y);
}

__global__ __launch_bounds__(T, 2)
void caps_routing_kernel(const float* __restrict__ u,
                         float* __restrict__ out) {
    __shared__ float   redS[NW * Pdim];
    __shared__ float   redW[NW];
    __shared__ __half2 vbufh[Pdim / 2];
    __shared__ float   miscS;

    const int t    = threadIdx.x;
    const int lane = t & 31;
    const int wid  = t >> 5;
    const int bid  = blockIdx.x;
    const int b    = bid >> 1;
    const int k    = bid & 1;

    const float4* U4 = reinterpret_cast<const float4*>(u) + (size_t)b * Rdim;

    // ---------------- Phase 1: u_ji -> fp16 registers (HFMA2) ----------------
    __half2 h[J][8];   // h[j][pp] = (p=2pp, p=2pp+1)

    #pragma unroll
    for (int j = 0; j < J; j++) {
        const int row  = j * 512 + t;
        const int rowc = row < Rdim ? row : Rdim - 1;   // clamp; W=0 masks tail
        float4 u4 = U4[rowc];
        __half2 u0 = __float2half2_rn(u4.x);
        __half2 u1 = __float2half2_rn(u4.y);
        __half2 u2 = __float2half2_rn(u4.z);
        __half2 u3 = __float2half2_rn(u4.w);

        const int4* Wp = W2dev + (size_t)(k * J + j) * 8 * 512 + t;
        int4 wa[8];
        #pragma unroll
        for (int c = 0; c < 8; c++) wa[c] = Wp[c * 512];   // 8 coalesced LDG.128
        const __half2* wh = reinterpret_cast<const __half2*>(wa);

        #pragma unroll
        for (int hc = 0; hc < 2; hc++) {
            #pragma unroll
            for (int i = 0; i < 4; i++) {
                __half2 acc = __hmul2(u3, wh[(6 + hc) * 4 + i]);
                acc = __hfma2(u2, wh[(4 + hc) * 4 + i], acc);
                acc = __hfma2(u1, wh[(2 + hc) * 4 + i], acc);
                acc = __hfma2(u0, wh[(0 + hc) * 4 + i], acc);
                h[j][hc * 4 + i] = acc;
            }
        }
    }

    // ---------------- Phase 2: routing (lane-local rows) ----------------
    float d[J];
    #pragma unroll
    for (int j = 0; j < J; j++) d[j] = (j * 512 + t < Rdim) ? 0.f : -1.0e30f;

    __half2 vh[8];

    // ---- iteration 0: uniform c ----
    {
        float s[Pdim];
        #pragma unroll
        for (int pp = 0; pp < 8; pp++) {
            __half2 acc = h[0][pp];
            #pragma unroll
            for (int j = 1; j < J; j++) acc = __hadd2(acc, h[j][pp]);  // tail rows 0
            float2 f = __half22float2(acc);
            s[2 * pp]     = f.x;
            s[2 * pp + 1] = f.y;
        }
        blockReduceSZ(s, 0.f, false, 1.0f / (float)Rdim,
                      redS, redW, vbufh, &miscS, true, t, lane, wid);
        #pragma unroll
        for (int pp = 0; pp < 8; pp++) vh[pp] = vbufh[pp];
        #pragma unroll
        for (int j = 0; j < J; j++) d[j] += dot16h(h[j], vh);  // tail: h=0 -> +0
    }

    // ---- iterations 1, 2 (no max subtraction: |d| small; invalid -> e=0) ----
    #pragma unroll
    for (int it = 1; it < 3; ++it) {
        float s[Pdim];
        #pragma unroll
        for (int p = 0; p < Pdim; p++) s[p] = 0.f;
        float lsum = 0.f;
        #pragma unroll
        for (int j = 0; j < J; j++) {
            float e = __expf(d[j]);   // invalid rows: d=-1e30 -> e=0
            lsum += e;
            #pragma unroll
            for (int pp = 0; pp < 8; pp++) {
                float2 f = __half22float2(h[j][pp]);
                s[2 * pp]     = fmaf(e, f.x, s[2 * pp]);
                s[2 * pp + 1] = fmaf(e, f.y, s[2 * pp + 1]);
            }
        }
        blockReduceSZ(s, lsum, true, 0.f,
                      redS, redW, vbufh, &miscS, it != 2, t, lane, wid);

        if (it == 2) break;
        #pragma unroll
        for (int pp = 0; pp < 8; pp++) vh[pp] = vbufh[pp];
        #pragma unroll
        for (int j = 0; j < J; j++) d[j] += dot16h(h[j], vh);
    }

    if (t == 0) {
        const float nrm = miscS;
        out[bid] = nrm / (1.f + nrm);
    }
}

extern "C" void kernel_launch(void* const* d_in, const int* in_sizes, int n_in,
                              void* d_out, int out_size) {
    const float* u = (const float*)d_in[0];   // [B, R, M] fp32
    const float* W = (const float*)d_in[1];   // [K, R, M, P] fp32
    float* out = (float*)d_out;               // [B, K] fp32

    convert_w_kernel<<<(WCONV + 255) / 256, 256>>>(W);
    caps_routing_kernel<<<Bdim * Kdim, T>>>(u, out);
}